// round 1
// baseline (speedup 1.0000x reference)
#include <cuda_runtime.h>
#include <cstddef>

// ---------------- problem constants ----------------
constexpr int NN   = 102400;    // nodes
constexpr int EE   = 3276800;   // edges
constexpr int NGRF = 256;       // graphs
constexpr int NC   = 9;         // classes

// ---------------- device scratch (no allocs allowed) ----------------
__device__ float  g_deg[NN];            // degree, then dinv in-place
__device__ float  g_lapw[EE];           // -dinv[s]*w*dinv[d]
__device__ float4 g_bufA[NN * 8];       // [N,32]
__device__ float4 g_bufB[NN * 8];       // [N,32] (projected y1, reused every layer)
__device__ float4 g_bufC[NN * 8];       // [N,32]
__device__ float4 g_bufD[NN * 4];       // [N,16]
__device__ float  g_f1[256 * 256];
__device__ float  g_f2[256 * 128];

__device__ __forceinline__ float* buf_ptr(int id) {
    switch (id) {
        case 0: return reinterpret_cast<float*>(g_bufA);
        case 1: return reinterpret_cast<float*>(g_bufB);
        case 2: return reinterpret_cast<float*>(g_bufC);
        case 3: return reinterpret_cast<float*>(g_bufD);
        case 4: return g_f1;
        default: return g_f2;
    }
}

// ---------------- graph prep ----------------
__global__ void k_deg_zero() {
    int i = blockIdx.x * 256 + threadIdx.x;
    if (i < NN) g_deg[i] = 0.f;
}

__global__ void k_deg_acc(const int* __restrict__ ei, const float* __restrict__ ew) {
    int e = blockIdx.x * 256 + threadIdx.x;
    if (e < EE) atomicAdd(&g_deg[ei[e]], ew[e]);
}

__global__ void k_dinv() {
    int i = blockIdx.x * 256 + threadIdx.x;
    if (i < NN) {
        float d = g_deg[i];
        g_deg[i] = (d > 0.f) ? rsqrtf(d) : 0.f;
    }
}

__global__ void k_lapw(const int* __restrict__ ei, const float* __restrict__ ew) {
    int e = blockIdx.x * 256 + threadIdx.x;
    if (e < EE) {
        int s = ei[e];
        int d = ei[EE + e];
        g_lapw[e] = -(g_deg[s] * ew[e] * g_deg[d]);
    }
}

// ---------------- conv projection GEMM ----------------
// y0 = relu?(h) @ W0 + b      (also serves as the aggregation accumulator)
// y1 = relu?(h) @ W1
// Thread computes 4 nodes x 8 output cols x both matrices.
template<int IN, int OUT, bool RELU, int HSRC, int Y0DST, int Y1DST>
__global__ void k_conv_gemm(const float* __restrict__ hx,
                            const float* __restrict__ W0g,
                            const float* __restrict__ W1g,
                            const float* __restrict__ bg)
{
    constexpr int NT  = (IN == 64) ? 64 : 128;  // nodes per block
    constexpr int NGr = NT / 4;                 // node groups (4 nodes each)
    constexpr int JG  = OUT / 8;                // j groups (8 cols each)
    constexpr int TPB = NGr * JG;

    __shared__ float sh[NT][IN + 1];
    __shared__ float sW0[IN * OUT];
    __shared__ float sW1[IN * OUT];
    __shared__ float sb[OUT];

    const float* hin = (HSRC < 0) ? hx : buf_ptr(HSRC);
    float* y0 = buf_ptr(Y0DST);
    float* y1 = buf_ptr(Y1DST);

    const int node0 = blockIdx.x * NT;

    for (int i = threadIdx.x; i < IN * OUT; i += TPB) {
        sW0[i] = W0g[i];
        sW1[i] = W1g[i];
    }
    if (threadIdx.x < OUT) sb[threadIdx.x] = bg[threadIdx.x];

    // stage h tile (coalesced float4 global reads, relu on load)
    for (int i = threadIdx.x; i < NT * (IN / 4); i += TPB) {
        int n  = i / (IN / 4);
        int k4 = (i % (IN / 4)) * 4;
        float4 v = *reinterpret_cast<const float4*>(&hin[(size_t)(node0 + n) * IN + k4]);
        if (RELU) {
            v.x = fmaxf(v.x, 0.f); v.y = fmaxf(v.y, 0.f);
            v.z = fmaxf(v.z, 0.f); v.w = fmaxf(v.w, 0.f);
        }
        sh[n][k4 + 0] = v.x; sh[n][k4 + 1] = v.y;
        sh[n][k4 + 2] = v.z; sh[n][k4 + 3] = v.w;
    }
    __syncthreads();

    const int g  = threadIdx.x % NGr;
    const int j0 = (threadIdx.x / NGr) * 8;

    float a0[4][8], a1[4][8];
    #pragma unroll
    for (int n = 0; n < 4; n++)
        #pragma unroll
        for (int j = 0; j < 8; j++) { a0[n][j] = 0.f; a1[n][j] = 0.f; }

    #pragma unroll 4
    for (int k = 0; k < IN; k++) {
        float hh[4];
        #pragma unroll
        for (int n = 0; n < 4; n++) hh[n] = sh[g * 4 + n][k];
        float w0[8], w1[8];
        reinterpret_cast<float4*>(w0)[0] = reinterpret_cast<const float4*>(&sW0[k * OUT + j0])[0];
        reinterpret_cast<float4*>(w0)[1] = reinterpret_cast<const float4*>(&sW0[k * OUT + j0])[1];
        reinterpret_cast<float4*>(w1)[0] = reinterpret_cast<const float4*>(&sW1[k * OUT + j0])[0];
        reinterpret_cast<float4*>(w1)[1] = reinterpret_cast<const float4*>(&sW1[k * OUT + j0])[1];
        #pragma unroll
        for (int n = 0; n < 4; n++)
            #pragma unroll
            for (int j = 0; j < 8; j++) {
                a0[n][j] += hh[n] * w0[j];
                a1[n][j] += hh[n] * w1[j];
            }
    }

    #pragma unroll
    for (int n = 0; n < 4; n++) {
        int node = node0 + g * 4 + n;
        float4 o0a, o0b, o1a, o1b;
        o0a.x = a0[n][0] + sb[j0 + 0]; o0a.y = a0[n][1] + sb[j0 + 1];
        o0a.z = a0[n][2] + sb[j0 + 2]; o0a.w = a0[n][3] + sb[j0 + 3];
        o0b.x = a0[n][4] + sb[j0 + 4]; o0b.y = a0[n][5] + sb[j0 + 5];
        o0b.z = a0[n][6] + sb[j0 + 6]; o0b.w = a0[n][7] + sb[j0 + 7];
        o1a.x = a1[n][0]; o1a.y = a1[n][1]; o1a.z = a1[n][2]; o1a.w = a1[n][3];
        o1b.x = a1[n][4]; o1b.y = a1[n][5]; o1b.z = a1[n][6]; o1b.w = a1[n][7];
        *reinterpret_cast<float4*>(&y0[(size_t)node * OUT + j0])     = o0a;
        *reinterpret_cast<float4*>(&y0[(size_t)node * OUT + j0 + 4]) = o0b;
        *reinterpret_cast<float4*>(&y1[(size_t)node * OUT + j0])     = o1a;
        *reinterpret_cast<float4*>(&y1[(size_t)node * OUT + j0 + 4]) = o1b;
    }
}

// ---------------- edge aggregation: acc[dst] += lapw * y1[src] ----------------
// 8 (or 4) consecutive threads per edge -> fully coalesced 128B row access.
template<int W, int YSRC, int ADST>
__global__ void k_edge(const int* __restrict__ ei) {
    constexpr int CPE = W / 4;               // float4 chunks per edge
    int idx = blockIdx.x * 256 + threadIdx.x;  // exact grid: EE*CPE threads
    int e = idx / CPE;
    int c = idx % CPE;
    const float* y1 = buf_ptr(YSRC);
    float* acc = buf_ptr(ADST);
    int s = ei[e];
    int d = ei[EE + e];
    float w = g_lapw[e];
    float4 v = *reinterpret_cast<const float4*>(&y1[(size_t)s * W + c * 4]);
    v.x *= w; v.y *= w; v.z *= w; v.w *= w;
    float* p = &acc[(size_t)d * W + c * 4];
    asm volatile("red.global.add.v4.f32 [%0], {%1,%2,%3,%4};"
                 :: "l"(p), "f"(v.x), "f"(v.y), "f"(v.z), "f"(v.w)
                 : "memory");
}

// ---------------- FC layers ----------------
template<int CDST>
__global__ void k_fc_init(const float* __restrict__ bias, int M, int Ncols) {
    int i = blockIdx.x * 256 + threadIdx.x;
    if (i < M * Ncols) buf_ptr(CDST)[i] = bias[i % Ncols];
}

// split-K tiled GEMM: C(64x64 tile) += A[m0:m0+64, kslice] @ B[kslice, n0:n0+64]
template<bool ARELU, int ASRC, int CDST>
__global__ void k_fc_gemm(const float* __restrict__ Aarg,
                          const float* __restrict__ B,
                          int M, int Ncols, int K, int Kper)
{
    const float* A = (ASRC < 0) ? Aarg : buf_ptr(ASRC);
    float* C = buf_ptr(CDST);
    __shared__ float As[8][68];
    __shared__ float Bs[8][64];
    const int n0 = blockIdx.x * 64;
    const int m0 = blockIdx.y * 64;
    const int kbase = blockIdx.z * Kper;
    const int tid = threadIdx.x;
    const int tx = tid % 16, ty = tid / 16;

    float acc[4][4];
    #pragma unroll
    for (int i = 0; i < 4; i++)
        #pragma unroll
        for (int j = 0; j < 4; j++) acc[i][j] = 0.f;

    for (int k0 = kbase; k0 < kbase + Kper; k0 += 8) {
        #pragma unroll
        for (int r = 0; r < 2; r++) {
            int idx = tid + r * 256;
            int mm = idx >> 3, kk = idx & 7;
            float v = A[(size_t)(m0 + mm) * K + k0 + kk];
            if (ARELU) v = fmaxf(v, 0.f);
            As[kk][mm] = v;
        }
        #pragma unroll
        for (int r = 0; r < 2; r++) {
            int idx = tid + r * 256;
            int kk = idx >> 6, nn = idx & 63;
            Bs[kk][nn] = B[(size_t)(k0 + kk) * Ncols + n0 + nn];
        }
        __syncthreads();
        #pragma unroll
        for (int kk = 0; kk < 8; kk++) {
            float4 a4 = *reinterpret_cast<const float4*>(&As[kk][ty * 4]);
            float4 b4 = *reinterpret_cast<const float4*>(&Bs[kk][tx * 4]);
            float a[4] = {a4.x, a4.y, a4.z, a4.w};
            float b[4] = {b4.x, b4.y, b4.z, b4.w};
            #pragma unroll
            for (int i = 0; i < 4; i++)
                #pragma unroll
                for (int j = 0; j < 4; j++) acc[i][j] += a[i] * b[j];
        }
        __syncthreads();
    }
    #pragma unroll
    for (int i = 0; i < 4; i++)
        #pragma unroll
        for (int j = 0; j < 4; j++)
            atomicAdd(&C[(size_t)(m0 + ty * 4 + i) * Ncols + n0 + tx * 4 + j], acc[i][j]);
}

__global__ void k_fc3(const float* __restrict__ w, const float* __restrict__ b,
                      float* __restrict__ out) {
    int idx = blockIdx.x * 256 + threadIdx.x;
    if (idx >= NGRF * NC) return;
    int g = idx / NC, j = idx % NC;
    float s = b[j];
    #pragma unroll 8
    for (int k = 0; k < 128; k++) s += g_f2[g * 128 + k] * w[k * NC + j];
    out[idx] = s;
}

// ---------------- launch ----------------
extern "C" void kernel_launch(void* const* d_in, const int* in_sizes, int n_in,
                              void* d_out, int out_size) {
    const float* x    = (const float*)d_in[0];
    const int*   ei   = (const int*)  d_in[1];
    const float* ew   = (const float*)d_in[2];
    const float* W10  = (const float*)d_in[3];
    const float* W11  = (const float*)d_in[4];
    const float* b1   = (const float*)d_in[5];
    const float* W20  = (const float*)d_in[6];
    const float* W21  = (const float*)d_in[7];
    const float* b2   = (const float*)d_in[8];
    const float* W30  = (const float*)d_in[9];
    const float* W31  = (const float*)d_in[10];
    const float* b3   = (const float*)d_in[11];
    const float* fc1w = (const float*)d_in[12];
    const float* fc1b = (const float*)d_in[13];
    const float* fc2w = (const float*)d_in[14];
    const float* fc2b = (const float*)d_in[15];
    const float* fc3w = (const float*)d_in[16];
    const float* fc3b = (const float*)d_in[17];
    float* out = (float*)d_out;

    // graph prep
    k_deg_zero<<<NN / 256, 256>>>();
    k_deg_acc<<<EE / 256, 256>>>(ei, ew);
    k_dinv<<<NN / 256, 256>>>();
    k_lapw<<<EE / 256, 256>>>(ei, ew);

    // layer 1: x[N,64] -> bufA (y0=x@W0+b), bufB (y1=x@W1); aggregate into bufA
    k_conv_gemm<64, 32, false, -1, 0, 1><<<NN / 64, 64>>>(x, W10, W11, b1);
    k_edge<32, 1, 0><<<(EE * 8) / 256, 256>>>(ei);

    // layer 2: relu(bufA) -> bufC, bufB; aggregate into bufC
    k_conv_gemm<32, 32, true, 0, 2, 1><<<NN / 128, 128>>>(nullptr, W20, W21, b2);
    k_edge<32, 1, 2><<<(EE * 8) / 256, 256>>>(ei);

    // layer 3: relu(bufC) -> bufD, bufB[:,:16]; aggregate into bufD
    k_conv_gemm<32, 16, true, 2, 3, 1><<<NN / 128, 64>>>(nullptr, W30, W31, b3);
    k_edge<16, 1, 3><<<(EE * 4) / 256, 256>>>(ei);

    // fc1: relu(bufD) as [256,6400] @ [6400,256] + b  (split-K = 8)
    k_fc_init<4><<<(256 * 256) / 256, 256>>>(fc1b, 256, 256);
    {
        dim3 grid(4, 4, 8);
        k_fc_gemm<true, 3, 4><<<grid, 256>>>(nullptr, fc1w, 256, 256, 6400, 800);
    }
    // fc2: [256,256] @ [256,128] + b  (split-K = 4)
    k_fc_init<5><<<(256 * 128) / 256, 256>>>(fc2b, 256, 128);
    {
        dim3 grid(2, 4, 4);
        k_fc_gemm<false, 4, 5><<<grid, 256>>>(nullptr, fc2w, 256, 128, 256, 64);
    }
    // fc3: [256,128] @ [128,9] + b -> out
    k_fc3<<<(NGRF * NC + 255) / 256, 256>>>(fc3w, fc3b, out);
}

// round 2
// speedup vs baseline: 1.1886x; 1.1886x over previous
#include <cuda_runtime.h>
#include <cstddef>

// ---------------- problem constants ----------------
constexpr int NN   = 102400;    // nodes
constexpr int EE   = 3276800;   // edges
constexpr int NGRF = 256;       // graphs
constexpr int NC   = 9;         // classes

// ---------------- device scratch (no allocs allowed) ----------------
__device__ float  g_deg[NN];            // degree sum, then dinv in-place
__device__ int    g_cnt[NN];            // in-degree histogram, then scatter cursor
__device__ int    g_off[NN + 1];        // CSR offsets (by dst)
__device__ int    g_bsum[128];          // scan block sums
__device__ int    g_bpre[128];          // scan block prefixes
__device__ int2   g_csr_sw[EE];         // packed {src, bits(lapw)} sorted by dst
__device__ float4 g_bufA[NN * 8];       // [N,32]  (aliased as [N,16] via id 6)
__device__ float4 g_bufB[NN * 8];       // [N,32]
__device__ float4 g_bufC[NN * 8];       // [N,32]
__device__ float4 g_bufD[NN * 4];       // [N,16]
__device__ float  g_f1[256 * 256];
__device__ float  g_f2[256 * 128];

__device__ __forceinline__ float* buf_ptr(int id) {
    switch (id) {
        case 0: return reinterpret_cast<float*>(g_bufA);
        case 1: return reinterpret_cast<float*>(g_bufB);
        case 2: return reinterpret_cast<float*>(g_bufC);
        case 3: return reinterpret_cast<float*>(g_bufD);
        case 4: return g_f1;
        case 5: return g_f2;
        default: return reinterpret_cast<float*>(g_bufA);  // 6: 16-wide alias
    }
}

// ---------------- graph prep ----------------
__global__ void k_init() {
    int i = blockIdx.x * 256 + threadIdx.x;
    if (i < NN) { g_deg[i] = 0.f; g_cnt[i] = 0; }
}

__global__ void k_deg_hist(const int* __restrict__ ei, const float* __restrict__ ew) {
    int e = blockIdx.x * 256 + threadIdx.x;
    if (e < EE) {
        atomicAdd(&g_deg[ei[e]], ew[e]);       // degree by src (weighted)
        atomicAdd(&g_cnt[ei[EE + e]], 1);      // in-degree histogram by dst
    }
}

__global__ void k_dinv() {
    int i = blockIdx.x * 256 + threadIdx.x;
    if (i < NN) {
        float d = g_deg[i];
        g_deg[i] = (d > 0.f) ? rsqrtf(d) : 0.f;
    }
}

// ---- 2-level exclusive scan of g_cnt[NN] into g_off ----
// level 1: 100 blocks x 1024 elems (256 thr x 4)
__global__ void k_scan1() {
    __shared__ int wsum[8];
    int base = blockIdx.x * 1024 + threadIdx.x * 4;
    int4 v = *reinterpret_cast<const int4*>(&g_cnt[base]);
    int s1 = v.x, s2 = s1 + v.y, s3 = s2 + v.z, tsum = s3 + v.w;
    int lane = threadIdx.x & 31, wid = threadIdx.x >> 5;
    int inc = tsum;
    #pragma unroll
    for (int o = 1; o < 32; o <<= 1) {
        int n = __shfl_up_sync(0xFFFFFFFFu, inc, o);
        if (lane >= o) inc += n;
    }
    if (lane == 31) wsum[wid] = inc;
    __syncthreads();
    int wpre = 0;
    #pragma unroll
    for (int i = 0; i < 8; i++) if (i < wid) wpre += wsum[i];
    int excl = wpre + inc - tsum;
    g_off[base + 0] = excl;
    g_off[base + 1] = excl + s1;
    g_off[base + 2] = excl + s2;
    g_off[base + 3] = excl + s3;
    if (threadIdx.x == 255) g_bsum[blockIdx.x] = wpre + inc;
}

// level 2: scan 100 block sums in one block
__global__ void k_scan2() {
    __shared__ int sm[128];
    int t = threadIdx.x;
    int v = (t < 100) ? g_bsum[t] : 0;
    sm[t] = v;
    __syncthreads();
    for (int o = 1; o < 128; o <<= 1) {
        int add = (t >= o) ? sm[t - o] : 0;
        __syncthreads();
        sm[t] += add;
        __syncthreads();
    }
    if (t < 100) g_bpre[t] = sm[t] - v;   // exclusive
}

// level 3: add back + reset cursor + sentinel
__global__ void k_scan3() {
    int i = blockIdx.x * 256 + threadIdx.x;
    if (i < NN) {
        g_off[i] += g_bpre[i >> 10];
        g_cnt[i] = 0;                      // cursor for scatter
    }
    if (i == 0) g_off[NN] = EE;
}

// scatter edges into CSR, computing lapw on the fly
__global__ void k_scatter(const int* __restrict__ ei, const float* __restrict__ ew) {
    int e = blockIdx.x * 256 + threadIdx.x;
    if (e >= EE) return;
    int s = ei[e];
    int d = ei[EE + e];
    float lw = -(g_deg[s] * ew[e] * g_deg[d]);   // g_deg holds dinv
    int pos = g_off[d] + atomicAdd(&g_cnt[d], 1);
    g_csr_sw[pos] = make_int2(s, __float_as_int(lw));
}

// ---------------- conv projection GEMM ----------------
// y0 = relu?(h) @ W0 + b ;  y1 = relu?(h) @ W1
template<int IN, int OUT, bool RELU, int HSRC, int Y0DST, int Y1DST>
__global__ void k_conv_gemm(const float* __restrict__ hx,
                            const float* __restrict__ W0g,
                            const float* __restrict__ W1g,
                            const float* __restrict__ bg)
{
    constexpr int NT  = (IN == 64) ? 64 : 128;
    constexpr int NGr = NT / 4;
    constexpr int JG  = OUT / 8;
    constexpr int TPB = NGr * JG;

    __shared__ float sh[NT][IN + 1];
    __shared__ float sW0[IN * OUT];
    __shared__ float sW1[IN * OUT];
    __shared__ float sb[OUT];

    const float* hin = (HSRC < 0) ? hx : buf_ptr(HSRC);
    float* y0 = buf_ptr(Y0DST);
    float* y1 = buf_ptr(Y1DST);
    const int node0 = blockIdx.x * NT;

    for (int i = threadIdx.x; i < IN * OUT; i += TPB) {
        sW0[i] = W0g[i];
        sW1[i] = W1g[i];
    }
    if (threadIdx.x < OUT) sb[threadIdx.x] = bg[threadIdx.x];

    for (int i = threadIdx.x; i < NT * (IN / 4); i += TPB) {
        int n  = i / (IN / 4);
        int k4 = (i % (IN / 4)) * 4;
        float4 v = *reinterpret_cast<const float4*>(&hin[(size_t)(node0 + n) * IN + k4]);
        if (RELU) {
            v.x = fmaxf(v.x, 0.f); v.y = fmaxf(v.y, 0.f);
            v.z = fmaxf(v.z, 0.f); v.w = fmaxf(v.w, 0.f);
        }
        sh[n][k4 + 0] = v.x; sh[n][k4 + 1] = v.y;
        sh[n][k4 + 2] = v.z; sh[n][k4 + 3] = v.w;
    }
    __syncthreads();

    const int g  = threadIdx.x % NGr;
    const int j0 = (threadIdx.x / NGr) * 8;

    float a0[4][8], a1[4][8];
    #pragma unroll
    for (int n = 0; n < 4; n++)
        #pragma unroll
        for (int j = 0; j < 8; j++) { a0[n][j] = 0.f; a1[n][j] = 0.f; }

    #pragma unroll 4
    for (int k = 0; k < IN; k++) {
        float hh[4];
        #pragma unroll
        for (int n = 0; n < 4; n++) hh[n] = sh[g * 4 + n][k];
        float w0[8], w1[8];
        reinterpret_cast<float4*>(w0)[0] = reinterpret_cast<const float4*>(&sW0[k * OUT + j0])[0];
        reinterpret_cast<float4*>(w0)[1] = reinterpret_cast<const float4*>(&sW0[k * OUT + j0])[1];
        reinterpret_cast<float4*>(w1)[0] = reinterpret_cast<const float4*>(&sW1[k * OUT + j0])[0];
        reinterpret_cast<float4*>(w1)[1] = reinterpret_cast<const float4*>(&sW1[k * OUT + j0])[1];
        #pragma unroll
        for (int n = 0; n < 4; n++)
            #pragma unroll
            for (int j = 0; j < 8; j++) {
                a0[n][j] += hh[n] * w0[j];
                a1[n][j] += hh[n] * w1[j];
            }
    }

    #pragma unroll
    for (int n = 0; n < 4; n++) {
        int node = node0 + g * 4 + n;
        float4 o0a, o0b, o1a, o1b;
        o0a.x = a0[n][0] + sb[j0 + 0]; o0a.y = a0[n][1] + sb[j0 + 1];
        o0a.z = a0[n][2] + sb[j0 + 2]; o0a.w = a0[n][3] + sb[j0 + 3];
        o0b.x = a0[n][4] + sb[j0 + 4]; o0b.y = a0[n][5] + sb[j0 + 5];
        o0b.z = a0[n][6] + sb[j0 + 6]; o0b.w = a0[n][7] + sb[j0 + 7];
        o1a.x = a1[n][0]; o1a.y = a1[n][1]; o1a.z = a1[n][2]; o1a.w = a1[n][3];
        o1b.x = a1[n][4]; o1b.y = a1[n][5]; o1b.z = a1[n][6]; o1b.w = a1[n][7];
        *reinterpret_cast<float4*>(&y0[(size_t)node * OUT + j0])     = o0a;
        *reinterpret_cast<float4*>(&y0[(size_t)node * OUT + j0 + 4]) = o0b;
        *reinterpret_cast<float4*>(&y1[(size_t)node * OUT + j0])     = o1a;
        *reinterpret_cast<float4*>(&y1[(size_t)node * OUT + j0 + 4]) = o1b;
    }
}

// ---------------- pull aggregation: out[n] = y0[n] + sum_e w_e * y1[src_e] ----------------
// W/4 threads per node, each owning one float4 column chunk. No atomics.
template<int W, int Y1SRC, int Y0SRC, int DST>
__global__ void k_pull() {
    constexpr int TPN = W / 4;
    constexpr int NPB = 256 / TPN;
    const int n = blockIdx.x * NPB + threadIdx.x / TPN;
    const int c = threadIdx.x % TPN;
    const float* __restrict__ y1 = buf_ptr(Y1SRC);
    const float* __restrict__ y0 = buf_ptr(Y0SRC);
    float* __restrict__ out = buf_ptr(DST);

    const int jb = g_off[n];
    const int je = g_off[n + 1];

    float4 acc = make_float4(0.f, 0.f, 0.f, 0.f);
    int j = jb;
    for (; j + 1 < je; j += 2) {
        int2 sw0 = g_csr_sw[j];
        int2 sw1 = g_csr_sw[j + 1];
        float4 v0 = *reinterpret_cast<const float4*>(&y1[(size_t)sw0.x * W + c * 4]);
        float4 v1 = *reinterpret_cast<const float4*>(&y1[(size_t)sw1.x * W + c * 4]);
        float w0 = __int_as_float(sw0.y);
        float w1 = __int_as_float(sw1.y);
        acc.x = fmaf(w0, v0.x, acc.x); acc.y = fmaf(w0, v0.y, acc.y);
        acc.z = fmaf(w0, v0.z, acc.z); acc.w = fmaf(w0, v0.w, acc.w);
        acc.x = fmaf(w1, v1.x, acc.x); acc.y = fmaf(w1, v1.y, acc.y);
        acc.z = fmaf(w1, v1.z, acc.z); acc.w = fmaf(w1, v1.w, acc.w);
    }
    if (j < je) {
        int2 sw = g_csr_sw[j];
        float4 v = *reinterpret_cast<const float4*>(&y1[(size_t)sw.x * W + c * 4]);
        float w = __int_as_float(sw.y);
        acc.x = fmaf(w, v.x, acc.x); acc.y = fmaf(w, v.y, acc.y);
        acc.z = fmaf(w, v.z, acc.z); acc.w = fmaf(w, v.w, acc.w);
    }
    float4 b = *reinterpret_cast<const float4*>(&y0[(size_t)n * W + c * 4]);
    acc.x += b.x; acc.y += b.y; acc.z += b.z; acc.w += b.w;
    *reinterpret_cast<float4*>(&out[(size_t)n * W + c * 4]) = acc;
}

// ---------------- FC layers ----------------
template<int CDST>
__global__ void k_fc_init(const float* __restrict__ bias, int M, int Ncols) {
    int i = blockIdx.x * 256 + threadIdx.x;
    if (i < M * Ncols) buf_ptr(CDST)[i] = bias[i % Ncols];
}

template<bool ARELU, int ASRC, int CDST>
__global__ void k_fc_gemm(const float* __restrict__ Aarg,
                          const float* __restrict__ B,
                          int M, int Ncols, int K, int Kper)
{
    const float* A = (ASRC < 0) ? Aarg : buf_ptr(ASRC);
    float* C = buf_ptr(CDST);
    __shared__ float As[8][68];
    __shared__ float Bs[8][64];
    const int n0 = blockIdx.x * 64;
    const int m0 = blockIdx.y * 64;
    const int kbase = blockIdx.z * Kper;
    const int tid = threadIdx.x;
    const int tx = tid % 16, ty = tid / 16;

    float acc[4][4];
    #pragma unroll
    for (int i = 0; i < 4; i++)
        #pragma unroll
        for (int j = 0; j < 4; j++) acc[i][j] = 0.f;

    for (int k0 = kbase; k0 < kbase + Kper; k0 += 8) {
        #pragma unroll
        for (int r = 0; r < 2; r++) {
            int idx = tid + r * 256;
            int mm = idx >> 3, kk = idx & 7;
            float v = A[(size_t)(m0 + mm) * K + k0 + kk];
            if (ARELU) v = fmaxf(v, 0.f);
            As[kk][mm] = v;
        }
        #pragma unroll
        for (int r = 0; r < 2; r++) {
            int idx = tid + r * 256;
            int kk = idx >> 6, nn = idx & 63;
            Bs[kk][nn] = B[(size_t)(k0 + kk) * Ncols + n0 + nn];
        }
        __syncthreads();
        #pragma unroll
        for (int kk = 0; kk < 8; kk++) {
            float4 a4 = *reinterpret_cast<const float4*>(&As[kk][ty * 4]);
            float4 b4 = *reinterpret_cast<const float4*>(&Bs[kk][tx * 4]);
            float a[4] = {a4.x, a4.y, a4.z, a4.w};
            float b[4] = {b4.x, b4.y, b4.z, b4.w};
            #pragma unroll
            for (int i = 0; i < 4; i++)
                #pragma unroll
                for (int j = 0; j < 4; j++) acc[i][j] += a[i] * b[j];
        }
        __syncthreads();
    }
    #pragma unroll
    for (int i = 0; i < 4; i++)
        #pragma unroll
        for (int j = 0; j < 4; j++)
            atomicAdd(&C[(size_t)(m0 + ty * 4 + i) * Ncols + n0 + tx * 4 + j], acc[i][j]);
}

__global__ void k_fc3(const float* __restrict__ w, const float* __restrict__ b,
                      float* __restrict__ out) {
    int idx = blockIdx.x * 256 + threadIdx.x;
    if (idx >= NGRF * NC) return;
    int g = idx / NC, j = idx % NC;
    float s = b[j];
    #pragma unroll 8
    for (int k = 0; k < 128; k++) s += g_f2[g * 128 + k] * w[k * NC + j];
    out[idx] = s;
}

// ---------------- launch ----------------
extern "C" void kernel_launch(void* const* d_in, const int* in_sizes, int n_in,
                              void* d_out, int out_size) {
    const float* x    = (const float*)d_in[0];
    const int*   ei   = (const int*)  d_in[1];
    const float* ew   = (const float*)d_in[2];
    const float* W10  = (const float*)d_in[3];
    const float* W11  = (const float*)d_in[4];
    const float* b1   = (const float*)d_in[5];
    const float* W20  = (const float*)d_in[6];
    const float* W21  = (const float*)d_in[7];
    const float* b2   = (const float*)d_in[8];
    const float* W30  = (const float*)d_in[9];
    const float* W31  = (const float*)d_in[10];
    const float* b3   = (const float*)d_in[11];
    const float* fc1w = (const float*)d_in[12];
    const float* fc1b = (const float*)d_in[13];
    const float* fc2w = (const float*)d_in[14];
    const float* fc2b = (const float*)d_in[15];
    const float* fc3w = (const float*)d_in[16];
    const float* fc3b = (const float*)d_in[17];
    float* out = (float*)d_out;

    // graph prep + CSR build
    k_init<<<NN / 256, 256>>>();
    k_deg_hist<<<EE / 256, 256>>>(ei, ew);
    k_dinv<<<NN / 256, 256>>>();
    k_scan1<<<100, 256>>>();
    k_scan2<<<1, 128>>>();
    k_scan3<<<NN / 256, 256>>>();
    k_scatter<<<EE / 256, 256>>>(ei, ew);

    // layer 1: x[N,64] -> y0:A, y1:B ; pull -> C
    k_conv_gemm<64, 32, false, -1, 0, 1><<<NN / 64, 64>>>(x, W10, W11, b1);
    k_pull<32, 1, 0, 2><<<NN / 32, 256>>>();

    // layer 2: relu(C) -> y0:A, y1:B ; pull -> C
    k_conv_gemm<32, 32, true, 2, 0, 1><<<NN / 128, 128>>>(nullptr, W20, W21, b2);
    k_pull<32, 1, 0, 2><<<NN / 32, 256>>>();

    // layer 3: relu(C) -> y0:D(16), y1:B(16) ; pull -> A-alias(16)
    k_conv_gemm<32, 16, true, 2, 3, 1><<<NN / 128, 64>>>(nullptr, W30, W31, b3);
    k_pull<16, 1, 3, 6><<<NN / 64, 256>>>();

    // fc1: relu(buf6) as [256,6400] @ [6400,256] + b  (split-K = 8)
    k_fc_init<4><<<(256 * 256) / 256, 256>>>(fc1b, 256, 256);
    {
        dim3 grid(4, 4, 8);
        k_fc_gemm<true, 6, 4><<<grid, 256>>>(nullptr, fc1w, 256, 256, 6400, 800);
    }
    // fc2: [256,256] @ [256,128] + b  (split-K = 4)
    k_fc_init<5><<<(256 * 128) / 256, 256>>>(fc2b, 256, 128);
    {
        dim3 grid(2, 4, 4);
        k_fc_gemm<false, 4, 5><<<grid, 256>>>(nullptr, fc2w, 256, 128, 256, 64);
    }
    // fc3: [256,128] @ [128,9] + b -> out
    k_fc3<<<(NGRF * NC + 255) / 256, 256>>>(fc3w, fc3b, out);
}

// round 3
// speedup vs baseline: 1.2516x; 1.0529x over previous
#include <cuda_runtime.h>
#include <cuda_fp16.h>
#include <cstddef>

// ---------------- problem constants ----------------
constexpr int NN   = 102400;    // nodes
constexpr int EE   = 3276800;   // edges
constexpr int NGRF = 256;       // graphs
constexpr int NC   = 9;         // classes

// ---------------- device scratch (no allocs allowed) ----------------
__device__ float  g_deg[NN];            // degree sum, then dinv in-place
__device__ int    g_cnt[NN];            // in-degree histogram
__device__ int    g_off[NN + 1];        // CSR offsets (by dst)
__device__ int    g_rank[EE];           // edge rank within its dst bucket
__device__ int    g_bsum[128];          // scan block sums
__device__ int    g_bpre[128];          // scan block prefixes
__device__ int2   g_csr_sw[EE];         // packed {src, bits(lapw)} sorted by dst
__device__ __half g_y1h[NN * 32];       // fp16 gather operand y1
__device__ float4 g_bufA[NN * 8];       // [N,32]  (also 16-wide alias id 6)
__device__ float4 g_bufC[NN * 8];       // [N,32]
__device__ float4 g_bufD[NN * 4];       // [N,16]
__device__ float  g_f1[256 * 256];
__device__ float  g_f2[256 * 128];

__device__ __forceinline__ float* buf_ptr(int id) {
    switch (id) {
        case 0: return reinterpret_cast<float*>(g_bufA);
        case 2: return reinterpret_cast<float*>(g_bufC);
        case 3: return reinterpret_cast<float*>(g_bufD);
        case 4: return g_f1;
        case 5: return g_f2;
        default: return reinterpret_cast<float*>(g_bufA);  // 6: 16-wide alias of A
    }
}

// ---------------- graph prep ----------------
__global__ void k_init() {
    int i = blockIdx.x * 256 + threadIdx.x;
    if (i < NN) { g_deg[i] = 0.f; g_cnt[i] = 0; }
}

// degree by src (weighted) + in-degree histogram by dst, recording each
// edge's rank within its dst bucket (the atomic's return value is free).
__global__ void k_deg_hist(const int* __restrict__ ei, const float* __restrict__ ew) {
    int e = blockIdx.x * 256 + threadIdx.x;
    if (e < EE) {
        atomicAdd(&g_deg[ei[e]], ew[e]);
        g_rank[e] = atomicAdd(&g_cnt[ei[EE + e]], 1);
    }
}

// ---- 2-level exclusive scan of g_cnt[NN] into g_off (+ fused dinv) ----
__global__ void k_scan1() {
    __shared__ int wsum[8];
    int base = blockIdx.x * 1024 + threadIdx.x * 4;
    // fused: deg -> dinv over the same range
    {
        float4 d = *reinterpret_cast<const float4*>(&g_deg[base]);
        d.x = (d.x > 0.f) ? rsqrtf(d.x) : 0.f;
        d.y = (d.y > 0.f) ? rsqrtf(d.y) : 0.f;
        d.z = (d.z > 0.f) ? rsqrtf(d.z) : 0.f;
        d.w = (d.w > 0.f) ? rsqrtf(d.w) : 0.f;
        *reinterpret_cast<float4*>(&g_deg[base]) = d;
    }
    int4 v = *reinterpret_cast<const int4*>(&g_cnt[base]);
    int s1 = v.x, s2 = s1 + v.y, s3 = s2 + v.z, tsum = s3 + v.w;
    int lane = threadIdx.x & 31, wid = threadIdx.x >> 5;
    int inc = tsum;
    #pragma unroll
    for (int o = 1; o < 32; o <<= 1) {
        int n = __shfl_up_sync(0xFFFFFFFFu, inc, o);
        if (lane >= o) inc += n;
    }
    if (lane == 31) wsum[wid] = inc;
    __syncthreads();
    int wpre = 0;
    #pragma unroll
    for (int i = 0; i < 8; i++) if (i < wid) wpre += wsum[i];
    int excl = wpre + inc - tsum;
    g_off[base + 0] = excl;
    g_off[base + 1] = excl + s1;
    g_off[base + 2] = excl + s2;
    g_off[base + 3] = excl + s3;
    if (threadIdx.x == 255) g_bsum[blockIdx.x] = wpre + inc;
}

__global__ void k_scan2() {
    __shared__ int sm[128];
    int t = threadIdx.x;
    int v = (t < 100) ? g_bsum[t] : 0;
    sm[t] = v;
    __syncthreads();
    for (int o = 1; o < 128; o <<= 1) {
        int add = (t >= o) ? sm[t - o] : 0;
        __syncthreads();
        sm[t] += add;
        __syncthreads();
    }
    if (t < 100) g_bpre[t] = sm[t] - v;
}

__global__ void k_scan3() {
    int i = blockIdx.x * 256 + threadIdx.x;
    if (i < NN) g_off[i] += g_bpre[i >> 10];
    if (i == 0) g_off[NN] = EE;
}

// atomic-free scatter: pos = off[dst] + rank[e]; lapw computed on the fly
__global__ void k_scatter(const int* __restrict__ ei, const float* __restrict__ ew) {
    int e = blockIdx.x * 256 + threadIdx.x;
    if (e >= EE) return;
    int s = ei[e];
    int d = ei[EE + e];
    float lw = -(g_deg[s] * ew[e] * g_deg[d]);   // g_deg holds dinv
    g_csr_sw[g_off[d] + g_rank[e]] = make_int2(s, __float_as_int(lw));
}

// ---------------- conv projection GEMM ----------------
// y0 = relu?(h) @ W0 + b  (fp32) ;  y1 = relu?(h) @ W1  (fp16 -> g_y1h)
template<int IN, int OUT, bool RELU, int HSRC, int Y0DST>
__global__ void k_conv_gemm(const float* __restrict__ hx,
                            const float* __restrict__ W0g,
                            const float* __restrict__ W1g,
                            const float* __restrict__ bg)
{
    constexpr int NT  = (IN == 64) ? 64 : 128;
    constexpr int NGr = NT / 4;
    constexpr int JG  = OUT / 8;
    constexpr int TPB = NGr * JG;

    __shared__ float sh[NT][IN + 1];
    __shared__ float sW0[IN * OUT];
    __shared__ float sW1[IN * OUT];
    __shared__ float sb[OUT];

    const float* hin = (HSRC < 0) ? hx : buf_ptr(HSRC);
    float* y0 = buf_ptr(Y0DST);
    const int node0 = blockIdx.x * NT;

    for (int i = threadIdx.x; i < IN * OUT; i += TPB) {
        sW0[i] = W0g[i];
        sW1[i] = W1g[i];
    }
    if (threadIdx.x < OUT) sb[threadIdx.x] = bg[threadIdx.x];

    for (int i = threadIdx.x; i < NT * (IN / 4); i += TPB) {
        int n  = i / (IN / 4);
        int k4 = (i % (IN / 4)) * 4;
        float4 v = *reinterpret_cast<const float4*>(&hin[(size_t)(node0 + n) * IN + k4]);
        if (RELU) {
            v.x = fmaxf(v.x, 0.f); v.y = fmaxf(v.y, 0.f);
            v.z = fmaxf(v.z, 0.f); v.w = fmaxf(v.w, 0.f);
        }
        sh[n][k4 + 0] = v.x; sh[n][k4 + 1] = v.y;
        sh[n][k4 + 2] = v.z; sh[n][k4 + 3] = v.w;
    }
    __syncthreads();

    const int g  = threadIdx.x % NGr;
    const int j0 = (threadIdx.x / NGr) * 8;

    float a0[4][8], a1[4][8];
    #pragma unroll
    for (int n = 0; n < 4; n++)
        #pragma unroll
        for (int j = 0; j < 8; j++) { a0[n][j] = 0.f; a1[n][j] = 0.f; }

    #pragma unroll 4
    for (int k = 0; k < IN; k++) {
        float hh[4];
        #pragma unroll
        for (int n = 0; n < 4; n++) hh[n] = sh[g * 4 + n][k];
        float w0[8], w1[8];
        reinterpret_cast<float4*>(w0)[0] = reinterpret_cast<const float4*>(&sW0[k * OUT + j0])[0];
        reinterpret_cast<float4*>(w0)[1] = reinterpret_cast<const float4*>(&sW0[k * OUT + j0])[1];
        reinterpret_cast<float4*>(w1)[0] = reinterpret_cast<const float4*>(&sW1[k * OUT + j0])[0];
        reinterpret_cast<float4*>(w1)[1] = reinterpret_cast<const float4*>(&sW1[k * OUT + j0])[1];
        #pragma unroll
        for (int n = 0; n < 4; n++)
            #pragma unroll
            for (int j = 0; j < 8; j++) {
                a0[n][j] += hh[n] * w0[j];
                a1[n][j] += hh[n] * w1[j];
            }
    }

    #pragma unroll
    for (int n = 0; n < 4; n++) {
        int node = node0 + g * 4 + n;
        float4 o0a, o0b;
        o0a.x = a0[n][0] + sb[j0 + 0]; o0a.y = a0[n][1] + sb[j0 + 1];
        o0a.z = a0[n][2] + sb[j0 + 2]; o0a.w = a0[n][3] + sb[j0 + 3];
        o0b.x = a0[n][4] + sb[j0 + 4]; o0b.y = a0[n][5] + sb[j0 + 5];
        o0b.z = a0[n][6] + sb[j0 + 6]; o0b.w = a0[n][7] + sb[j0 + 7];
        *reinterpret_cast<float4*>(&y0[(size_t)node * OUT + j0])     = o0a;
        *reinterpret_cast<float4*>(&y0[(size_t)node * OUT + j0 + 4]) = o0b;
        // y1 -> fp16, 8 values = one 16B store
        __half2 h01 = __float22half2_rn(make_float2(a1[n][0], a1[n][1]));
        __half2 h23 = __float22half2_rn(make_float2(a1[n][2], a1[n][3]));
        __half2 h45 = __float22half2_rn(make_float2(a1[n][4], a1[n][5]));
        __half2 h67 = __float22half2_rn(make_float2(a1[n][6], a1[n][7]));
        uint4 pk;
        pk.x = *reinterpret_cast<unsigned*>(&h01);
        pk.y = *reinterpret_cast<unsigned*>(&h23);
        pk.z = *reinterpret_cast<unsigned*>(&h45);
        pk.w = *reinterpret_cast<unsigned*>(&h67);
        *reinterpret_cast<uint4*>(&g_y1h[(size_t)node * OUT + j0]) = pk;
    }
}

// ---------------- pull aggregation ----------------
// out[n] = y0[n] + sum_e w_e * y1h[src_e] ; W/8 threads per node (16B fp16 gathers)
__device__ __forceinline__ void acc8(float* a, uint4 r, float w) {
    float2 f0 = __half22float2(*reinterpret_cast<__half2*>(&r.x));
    float2 f1 = __half22float2(*reinterpret_cast<__half2*>(&r.y));
    float2 f2 = __half22float2(*reinterpret_cast<__half2*>(&r.z));
    float2 f3 = __half22float2(*reinterpret_cast<__half2*>(&r.w));
    a[0] = fmaf(w, f0.x, a[0]); a[1] = fmaf(w, f0.y, a[1]);
    a[2] = fmaf(w, f1.x, a[2]); a[3] = fmaf(w, f1.y, a[3]);
    a[4] = fmaf(w, f2.x, a[4]); a[5] = fmaf(w, f2.y, a[5]);
    a[6] = fmaf(w, f3.x, a[6]); a[7] = fmaf(w, f3.y, a[7]);
}

template<int W, int Y0SRC, int DST>
__global__ void k_pull() {
    constexpr int TPN = W / 8;                 // threads per node
    constexpr int NPB = 256 / TPN;             // nodes per block
    const int n = blockIdx.x * NPB + threadIdx.x / TPN;
    const int c = threadIdx.x % TPN;           // 8-feature chunk
    const float* __restrict__ y0 = buf_ptr(Y0SRC);
    float* __restrict__ out = buf_ptr(DST);

    const int jb = g_off[n];
    const int je = g_off[n + 1];

    float acc[8];
    #pragma unroll
    for (int i = 0; i < 8; i++) acc[i] = 0.f;

    int j = jb;
    for (; j + 1 < je; j += 2) {
        int2 sw0 = __ldg(&g_csr_sw[j]);
        int2 sw1 = __ldg(&g_csr_sw[j + 1]);
        uint4 r0 = *reinterpret_cast<const uint4*>(&g_y1h[(size_t)sw0.x * W + c * 8]);
        uint4 r1 = *reinterpret_cast<const uint4*>(&g_y1h[(size_t)sw1.x * W + c * 8]);
        acc8(acc, r0, __int_as_float(sw0.y));
        acc8(acc, r1, __int_as_float(sw1.y));
    }
    if (j < je) {
        int2 sw = __ldg(&g_csr_sw[j]);
        uint4 r = *reinterpret_cast<const uint4*>(&g_y1h[(size_t)sw.x * W + c * 8]);
        acc8(acc, r, __int_as_float(sw.y));
    }

    float4 b0 = *reinterpret_cast<const float4*>(&y0[(size_t)n * W + c * 8]);
    float4 b1 = *reinterpret_cast<const float4*>(&y0[(size_t)n * W + c * 8 + 4]);
    float4 o0 = make_float4(acc[0] + b0.x, acc[1] + b0.y, acc[2] + b0.z, acc[3] + b0.w);
    float4 o1 = make_float4(acc[4] + b1.x, acc[5] + b1.y, acc[6] + b1.z, acc[7] + b1.w);
    *reinterpret_cast<float4*>(&out[(size_t)n * W + c * 8])     = o0;
    *reinterpret_cast<float4*>(&out[(size_t)n * W + c * 8 + 4]) = o1;
}

// ---------------- FC layers ----------------
template<int CDST>
__global__ void k_fc_init(const float* __restrict__ bias, int M, int Ncols) {
    int i = blockIdx.x * 256 + threadIdx.x;
    if (i < M * Ncols) buf_ptr(CDST)[i] = bias[i % Ncols];
}

template<bool ARELU, int ASRC, int CDST>
__global__ void k_fc_gemm(const float* __restrict__ Aarg,
                          const float* __restrict__ B,
                          int M, int Ncols, int K, int Kper)
{
    const float* A = (ASRC < 0) ? Aarg : buf_ptr(ASRC);
    float* C = buf_ptr(CDST);
    __shared__ float As[8][68];
    __shared__ float Bs[8][64];
    const int n0 = blockIdx.x * 64;
    const int m0 = blockIdx.y * 64;
    const int kbase = blockIdx.z * Kper;
    const int tid = threadIdx.x;
    const int tx = tid % 16, ty = tid / 16;

    float acc[4][4];
    #pragma unroll
    for (int i = 0; i < 4; i++)
        #pragma unroll
        for (int j = 0; j < 4; j++) acc[i][j] = 0.f;

    for (int k0 = kbase; k0 < kbase + Kper; k0 += 8) {
        #pragma unroll
        for (int r = 0; r < 2; r++) {
            int idx = tid + r * 256;
            int mm = idx >> 3, kk = idx & 7;
            float v = A[(size_t)(m0 + mm) * K + k0 + kk];
            if (ARELU) v = fmaxf(v, 0.f);
            As[kk][mm] = v;
        }
        #pragma unroll
        for (int r = 0; r < 2; r++) {
            int idx = tid + r * 256;
            int kk = idx >> 6, nn = idx & 63;
            Bs[kk][nn] = B[(size_t)(k0 + kk) * Ncols + n0 + nn];
        }
        __syncthreads();
        #pragma unroll
        for (int kk = 0; kk < 8; kk++) {
            float4 a4 = *reinterpret_cast<const float4*>(&As[kk][ty * 4]);
            float4 b4 = *reinterpret_cast<const float4*>(&Bs[kk][tx * 4]);
            float a[4] = {a4.x, a4.y, a4.z, a4.w};
            float b[4] = {b4.x, b4.y, b4.z, b4.w};
            #pragma unroll
            for (int i = 0; i < 4; i++)
                #pragma unroll
                for (int j = 0; j < 4; j++) acc[i][j] += a[i] * b[j];
        }
        __syncthreads();
    }
    #pragma unroll
    for (int i = 0; i < 4; i++)
        #pragma unroll
        for (int j = 0; j < 4; j++)
            atomicAdd(&C[(size_t)(m0 + ty * 4 + i) * Ncols + n0 + tx * 4 + j], acc[i][j]);
}

__global__ void k_fc3(const float* __restrict__ w, const float* __restrict__ b,
                      float* __restrict__ out) {
    int idx = blockIdx.x * 256 + threadIdx.x;
    if (idx >= NGRF * NC) return;
    int g = idx / NC, j = idx % NC;
    float s = b[j];
    #pragma unroll 8
    for (int k = 0; k < 128; k++) s += g_f2[g * 128 + k] * w[k * NC + j];
    out[idx] = s;
}

// ---------------- launch ----------------
extern "C" void kernel_launch(void* const* d_in, const int* in_sizes, int n_in,
                              void* d_out, int out_size) {
    const float* x    = (const float*)d_in[0];
    const int*   ei   = (const int*)  d_in[1];
    const float* ew   = (const float*)d_in[2];
    const float* W10  = (const float*)d_in[3];
    const float* W11  = (const float*)d_in[4];
    const float* b1   = (const float*)d_in[5];
    const float* W20  = (const float*)d_in[6];
    const float* W21  = (const float*)d_in[7];
    const float* b2   = (const float*)d_in[8];
    const float* W30  = (const float*)d_in[9];
    const float* W31  = (const float*)d_in[10];
    const float* b3   = (const float*)d_in[11];
    const float* fc1w = (const float*)d_in[12];
    const float* fc1b = (const float*)d_in[13];
    const float* fc2w = (const float*)d_in[14];
    const float* fc2b = (const float*)d_in[15];
    const float* fc3w = (const float*)d_in[16];
    const float* fc3b = (const float*)d_in[17];
    float* out = (float*)d_out;

    // graph prep + CSR build
    k_init<<<NN / 256, 256>>>();
    k_deg_hist<<<EE / 256, 256>>>(ei, ew);
    k_scan1<<<100, 256>>>();                 // also computes dinv
    k_scan2<<<1, 128>>>();
    k_scan3<<<NN / 256, 256>>>();
    k_scatter<<<EE / 256, 256>>>(ei, ew);

    // layer 1: x[N,64] -> y0:A, y1h ; pull -> C
    k_conv_gemm<64, 32, false, -1, 0><<<NN / 64, 64>>>(x, W10, W11, b1);
    k_pull<32, 0, 2><<<NN / 64, 256>>>();

    // layer 2: relu(C) -> y0:A, y1h ; pull -> C
    k_conv_gemm<32, 32, true, 2, 0><<<NN / 128, 128>>>(nullptr, W20, W21, b2);
    k_pull<32, 0, 2><<<NN / 64, 256>>>();

    // layer 3: relu(C) -> y0:D(16), y1h(16) ; pull -> A-alias(16)
    k_conv_gemm<32, 16, true, 2, 3><<<NN / 128, 64>>>(nullptr, W30, W31, b3);
    k_pull<16, 3, 6><<<NN / 128, 256>>>();

    // fc1: relu(buf6) as [256,6400] @ [6400,256] + b  (split-K = 8)
    k_fc_init<4><<<(256 * 256) / 256, 256>>>(fc1b, 256, 256);
    {
        dim3 grid(4, 4, 8);
        k_fc_gemm<true, 6, 4><<<grid, 256>>>(nullptr, fc1w, 256, 256, 6400, 800);
    }
    // fc2: [256,256] @ [256,128] + b  (split-K = 4)
    k_fc_init<5><<<(256 * 128) / 256, 256>>>(fc2b, 256, 128);
    {
        dim3 grid(2, 4, 4);
        k_fc_gemm<false, 4, 5><<<grid, 256>>>(nullptr, fc2w, 256, 128, 256, 64);
    }
    // fc3: [256,128] @ [128,9] + b -> out
    k_fc3<<<(NGRF * NC + 255) / 256, 256>>>(fc3w, fc3b, out);
}

// round 4
// speedup vs baseline: 1.2983x; 1.0374x over previous
#include <cuda_runtime.h>
#include <cuda_fp16.h>
#include <cstddef>

// ---------------- problem constants ----------------
constexpr int NN   = 102400;    // nodes
constexpr int EE   = 3276800;   // edges
constexpr int NGRF = 256;       // graphs
constexpr int NC   = 9;         // classes

// ---------------- device scratch (no allocs allowed) ----------------
__device__ float  g_deg[NN];            // degree sum, then dinv in-place
__device__ int    g_cnt[NN];            // in-degree histogram
__device__ int    g_off[NN + 1];        // CSR offsets (by dst)
__device__ int    g_rank[EE];           // edge rank within its dst bucket
__device__ int    g_bsum[128];          // scan block sums
__device__ int4   g_csr_pair[EE / 2];   // {src,w} pairs, 16B-aligned view
__device__ __half g_y1h[NN * 32];       // fp16 gather operand y1
__device__ float4 g_bufA[NN * 8];       // [N,32]  (also 16-wide alias id 6)
__device__ float4 g_bufC[NN * 8];       // [N,32]
__device__ float4 g_bufD[NN * 4];       // [N,16]
__device__ float  g_f1[256 * 256];
__device__ float  g_f2[256 * 128];

__device__ __forceinline__ float* buf_ptr(int id) {
    switch (id) {
        case 0: return reinterpret_cast<float*>(g_bufA);
        case 2: return reinterpret_cast<float*>(g_bufC);
        case 3: return reinterpret_cast<float*>(g_bufD);
        case 4: return g_f1;
        case 5: return g_f2;
        default: return reinterpret_cast<float*>(g_bufA);  // 6: 16-wide alias of A
    }
}

// ---------------- graph prep ----------------
__global__ void k_init() {
    int i = blockIdx.x * 256 + threadIdx.x;
    if (i < NN) { g_deg[i] = 0.f; g_cnt[i] = 0; }
}

// degree by src (weighted) + in-degree histogram by dst, recording each
// edge's rank within its dst bucket (the atomic's return value is free).
__global__ void k_deg_hist(const int* __restrict__ ei, const float* __restrict__ ew) {
    int e = blockIdx.x * 256 + threadIdx.x;
    if (e < EE) {
        atomicAdd(&g_deg[ei[e]], ew[e]);
        g_rank[e] = atomicAdd(&g_cnt[ei[EE + e]], 1);
    }
}

// ---- scan of g_cnt[NN] into g_off (+ fused dinv) ----
// level 1: 100 blocks x 1024 elems; writes per-block exclusive scan + block sums
__global__ void k_scan1() {
    __shared__ int wsum[8];
    int base = blockIdx.x * 1024 + threadIdx.x * 4;
    {   // fused: deg -> dinv over the same range
        float4 d = *reinterpret_cast<const float4*>(&g_deg[base]);
        d.x = (d.x > 0.f) ? rsqrtf(d.x) : 0.f;
        d.y = (d.y > 0.f) ? rsqrtf(d.y) : 0.f;
        d.z = (d.z > 0.f) ? rsqrtf(d.z) : 0.f;
        d.w = (d.w > 0.f) ? rsqrtf(d.w) : 0.f;
        *reinterpret_cast<float4*>(&g_deg[base]) = d;
    }
    int4 v = *reinterpret_cast<const int4*>(&g_cnt[base]);
    int s1 = v.x, s2 = s1 + v.y, s3 = s2 + v.z, tsum = s3 + v.w;
    int lane = threadIdx.x & 31, wid = threadIdx.x >> 5;
    int inc = tsum;
    #pragma unroll
    for (int o = 1; o < 32; o <<= 1) {
        int n = __shfl_up_sync(0xFFFFFFFFu, inc, o);
        if (lane >= o) inc += n;
    }
    if (lane == 31) wsum[wid] = inc;
    __syncthreads();
    int wpre = 0;
    #pragma unroll
    for (int i = 0; i < 8; i++) if (i < wid) wpre += wsum[i];
    int excl = wpre + inc - tsum;
    g_off[base + 0] = excl;
    g_off[base + 1] = excl + s1;
    g_off[base + 2] = excl + s2;
    g_off[base + 3] = excl + s3;
    if (threadIdx.x == 255) g_bsum[blockIdx.x] = wpre + inc;
}

// level 2+3 fused: each block adds the prefix of g_bsum for its scan1-region
__global__ void k_scan23() {
    const int i = blockIdx.x * 256 + threadIdx.x;
    const int blk = blockIdx.x >> 2;   // scan1 block index (1024 nodes each)
    const int lane = threadIdx.x & 31;
    int partial = 0;
    for (int t = lane; t < blk; t += 32) partial += g_bsum[t];
    #pragma unroll
    for (int o = 16; o; o >>= 1) partial += __shfl_xor_sync(0xFFFFFFFFu, partial, o);
    g_off[i] += partial;
    if (i == 0) g_off[NN] = EE;
}

// atomic-free scatter: pos = off[dst] + rank[e]; lapw computed on the fly
__global__ void k_scatter(const int* __restrict__ ei, const float* __restrict__ ew) {
    int e = blockIdx.x * 256 + threadIdx.x;
    if (e >= EE) return;
    int s = ei[e];
    int d = ei[EE + e];
    float lw = -(g_deg[s] * ew[e] * g_deg[d]);   // g_deg holds dinv
    reinterpret_cast<int2*>(g_csr_pair)[g_off[d] + g_rank[e]] =
        make_int2(s, __float_as_int(lw));
}

// ---------------- conv projection GEMM ----------------
// y0 = relu?(h) @ W0 + b  (fp32) ;  y1 = relu?(h) @ W1  (fp16 -> g_y1h)
template<int IN, int OUT, bool RELU, int HSRC, int Y0DST>
__global__ void k_conv_gemm(const float* __restrict__ hx,
                            const float* __restrict__ W0g,
                            const float* __restrict__ W1g,
                            const float* __restrict__ bg)
{
    constexpr int NT  = (IN == 64) ? 64 : 128;
    constexpr int NGr = NT / 4;
    constexpr int JG  = OUT / 8;
    constexpr int TPB = NGr * JG;

    __shared__ float sh[NT][IN + 1];
    __shared__ float sW0[IN * OUT];
    __shared__ float sW1[IN * OUT];
    __shared__ float sb[OUT];

    const float* hin = (HSRC < 0) ? hx : buf_ptr(HSRC);
    float* y0 = buf_ptr(Y0DST);
    const int node0 = blockIdx.x * NT;

    for (int i = threadIdx.x; i < IN * OUT; i += TPB) {
        sW0[i] = W0g[i];
        sW1[i] = W1g[i];
    }
    if (threadIdx.x < OUT) sb[threadIdx.x] = bg[threadIdx.x];

    for (int i = threadIdx.x; i < NT * (IN / 4); i += TPB) {
        int n  = i / (IN / 4);
        int k4 = (i % (IN / 4)) * 4;
        float4 v = *reinterpret_cast<const float4*>(&hin[(size_t)(node0 + n) * IN + k4]);
        if (RELU) {
            v.x = fmaxf(v.x, 0.f); v.y = fmaxf(v.y, 0.f);
            v.z = fmaxf(v.z, 0.f); v.w = fmaxf(v.w, 0.f);
        }
        sh[n][k4 + 0] = v.x; sh[n][k4 + 1] = v.y;
        sh[n][k4 + 2] = v.z; sh[n][k4 + 3] = v.w;
    }
    __syncthreads();

    const int g  = threadIdx.x % NGr;
    const int j0 = (threadIdx.x / NGr) * 8;

    float a0[4][8], a1[4][8];
    #pragma unroll
    for (int n = 0; n < 4; n++)
        #pragma unroll
        for (int j = 0; j < 8; j++) { a0[n][j] = 0.f; a1[n][j] = 0.f; }

    #pragma unroll 4
    for (int k = 0; k < IN; k++) {
        float hh[4];
        #pragma unroll
        for (int n = 0; n < 4; n++) hh[n] = sh[g * 4 + n][k];
        float w0[8], w1[8];
        reinterpret_cast<float4*>(w0)[0] = reinterpret_cast<const float4*>(&sW0[k * OUT + j0])[0];
        reinterpret_cast<float4*>(w0)[1] = reinterpret_cast<const float4*>(&sW0[k * OUT + j0])[1];
        reinterpret_cast<float4*>(w1)[0] = reinterpret_cast<const float4*>(&sW1[k * OUT + j0])[0];
        reinterpret_cast<float4*>(w1)[1] = reinterpret_cast<const float4*>(&sW1[k * OUT + j0])[1];
        #pragma unroll
        for (int n = 0; n < 4; n++)
            #pragma unroll
            for (int j = 0; j < 8; j++) {
                a0[n][j] += hh[n] * w0[j];
                a1[n][j] += hh[n] * w1[j];
            }
    }

    #pragma unroll
    for (int n = 0; n < 4; n++) {
        int node = node0 + g * 4 + n;
        float4 o0a, o0b;
        o0a.x = a0[n][0] + sb[j0 + 0]; o0a.y = a0[n][1] + sb[j0 + 1];
        o0a.z = a0[n][2] + sb[j0 + 2]; o0a.w = a0[n][3] + sb[j0 + 3];
        o0b.x = a0[n][4] + sb[j0 + 4]; o0b.y = a0[n][5] + sb[j0 + 5];
        o0b.z = a0[n][6] + sb[j0 + 6]; o0b.w = a0[n][7] + sb[j0 + 7];
        *reinterpret_cast<float4*>(&y0[(size_t)node * OUT + j0])     = o0a;
        *reinterpret_cast<float4*>(&y0[(size_t)node * OUT + j0 + 4]) = o0b;
        __half2 h01 = __float22half2_rn(make_float2(a1[n][0], a1[n][1]));
        __half2 h23 = __float22half2_rn(make_float2(a1[n][2], a1[n][3]));
        __half2 h45 = __float22half2_rn(make_float2(a1[n][4], a1[n][5]));
        __half2 h67 = __float22half2_rn(make_float2(a1[n][6], a1[n][7]));
        uint4 pk;
        pk.x = *reinterpret_cast<unsigned*>(&h01);
        pk.y = *reinterpret_cast<unsigned*>(&h23);
        pk.z = *reinterpret_cast<unsigned*>(&h45);
        pk.w = *reinterpret_cast<unsigned*>(&h67);
        *reinterpret_cast<uint4*>(&g_y1h[(size_t)node * OUT + j0]) = pk;
    }
}

// ---------------- pull aggregation ----------------
// out[n] = y0[n] + sum_e w_e * y1h[src_e] ; W/8 threads per node (16B fp16 gathers)
// 4 edges per round: 2x int4 CSR loads + 4 independent row gathers (MLP ~6).
__device__ __forceinline__ void acc8(float* a, uint4 r, float w) {
    float2 f0 = __half22float2(*reinterpret_cast<__half2*>(&r.x));
    float2 f1 = __half22float2(*reinterpret_cast<__half2*>(&r.y));
    float2 f2 = __half22float2(*reinterpret_cast<__half2*>(&r.z));
    float2 f3 = __half22float2(*reinterpret_cast<__half2*>(&r.w));
    a[0] = fmaf(w, f0.x, a[0]); a[1] = fmaf(w, f0.y, a[1]);
    a[2] = fmaf(w, f1.x, a[2]); a[3] = fmaf(w, f1.y, a[3]);
    a[4] = fmaf(w, f2.x, a[4]); a[5] = fmaf(w, f2.y, a[5]);
    a[6] = fmaf(w, f3.x, a[6]); a[7] = fmaf(w, f3.y, a[7]);
}

template<int W, int Y0SRC, int DST>
__global__ void k_pull() {
    constexpr int TPN = W / 8;                 // threads per node
    constexpr int NPB = 256 / TPN;             // nodes per block
    const int n = blockIdx.x * NPB + threadIdx.x / TPN;
    const int c = threadIdx.x % TPN;           // 8-feature chunk
    const float* __restrict__ y0 = buf_ptr(Y0SRC);
    float* __restrict__ out = buf_ptr(DST);
    const int2* __restrict__ csr = reinterpret_cast<const int2*>(g_csr_pair);

    const int jb = g_off[n];
    const int je = g_off[n + 1];

    float acc[8];
    #pragma unroll
    for (int i = 0; i < 8; i++) acc[i] = 0.f;

    int j = jb;
    if ((j & 1) && j < je) {                   // align to even for int4 loads
        int2 sw = csr[j];
        uint4 r = *reinterpret_cast<const uint4*>(&g_y1h[(size_t)sw.x * W + c * 8]);
        acc8(acc, r, __int_as_float(sw.y));
        j++;
    }
    for (; j + 4 <= je; j += 4) {
        int4 p0 = g_csr_pair[j >> 1];          // edges j, j+1
        int4 p1 = g_csr_pair[(j >> 1) + 1];    // edges j+2, j+3
        uint4 r0 = *reinterpret_cast<const uint4*>(&g_y1h[(size_t)p0.x * W + c * 8]);
        uint4 r1 = *reinterpret_cast<const uint4*>(&g_y1h[(size_t)p0.z * W + c * 8]);
        uint4 r2 = *reinterpret_cast<const uint4*>(&g_y1h[(size_t)p1.x * W + c * 8]);
        uint4 r3 = *reinterpret_cast<const uint4*>(&g_y1h[(size_t)p1.z * W + c * 8]);
        acc8(acc, r0, __int_as_float(p0.y));
        acc8(acc, r1, __int_as_float(p0.w));
        acc8(acc, r2, __int_as_float(p1.y));
        acc8(acc, r3, __int_as_float(p1.w));
    }
    for (; j < je; j++) {
        int2 sw = csr[j];
        uint4 r = *reinterpret_cast<const uint4*>(&g_y1h[(size_t)sw.x * W + c * 8]);
        acc8(acc, r, __int_as_float(sw.y));
    }

    float4 b0 = *reinterpret_cast<const float4*>(&y0[(size_t)n * W + c * 8]);
    float4 b1 = *reinterpret_cast<const float4*>(&y0[(size_t)n * W + c * 8 + 4]);
    float4 o0 = make_float4(acc[0] + b0.x, acc[1] + b0.y, acc[2] + b0.z, acc[3] + b0.w);
    float4 o1 = make_float4(acc[4] + b1.x, acc[5] + b1.y, acc[6] + b1.z, acc[7] + b1.w);
    *reinterpret_cast<float4*>(&out[(size_t)n * W + c * 8])     = o0;
    *reinterpret_cast<float4*>(&out[(size_t)n * W + c * 8 + 4]) = o1;
}

// ---------------- FC layers ----------------
template<int CDST>
__global__ void k_fc_init(const float* __restrict__ bias, int M, int Ncols) {
    int i = blockIdx.x * 256 + threadIdx.x;
    if (i < M * Ncols) buf_ptr(CDST)[i] = bias[i % Ncols];
}

template<bool ARELU, int ASRC, int CDST>
__global__ void k_fc_gemm(const float* __restrict__ Aarg,
                          const float* __restrict__ B,
                          int M, int Ncols, int K, int Kper)
{
    const float* A = (ASRC < 0) ? Aarg : buf_ptr(ASRC);
    float* C = buf_ptr(CDST);
    __shared__ float As[8][68];
    __shared__ float Bs[8][64];
    const int n0 = blockIdx.x * 64;
    const int m0 = blockIdx.y * 64;
    const int kbase = blockIdx.z * Kper;
    const int tid = threadIdx.x;
    const int tx = tid % 16, ty = tid / 16;

    float acc[4][4];
    #pragma unroll
    for (int i = 0; i < 4; i++)
        #pragma unroll
        for (int j = 0; j < 4; j++) acc[i][j] = 0.f;

    for (int k0 = kbase; k0 < kbase + Kper; k0 += 8) {
        #pragma unroll
        for (int r = 0; r < 2; r++) {
            int idx = tid + r * 256;
            int mm = idx >> 3, kk = idx & 7;
            float v = A[(size_t)(m0 + mm) * K + k0 + kk];
            if (ARELU) v = fmaxf(v, 0.f);
            As[kk][mm] = v;
        }
        #pragma unroll
        for (int r = 0; r < 2; r++) {
            int idx = tid + r * 256;
            int kk = idx >> 6, nn = idx & 63;
            Bs[kk][nn] = B[(size_t)(k0 + kk) * Ncols + n0 + nn];
        }
        __syncthreads();
        #pragma unroll
        for (int kk = 0; kk < 8; kk++) {
            float4 a4 = *reinterpret_cast<const float4*>(&As[kk][ty * 4]);
            float4 b4 = *reinterpret_cast<const float4*>(&Bs[kk][tx * 4]);
            float a[4] = {a4.x, a4.y, a4.z, a4.w};
            float b[4] = {b4.x, b4.y, b4.z, b4.w};
            #pragma unroll
            for (int i = 0; i < 4; i++)
                #pragma unroll
                for (int j = 0; j < 4; j++) acc[i][j] += a[i] * b[j];
        }
        __syncthreads();
    }
    #pragma unroll
    for (int i = 0; i < 4; i++)
        #pragma unroll
        for (int j = 0; j < 4; j++)
            atomicAdd(&C[(size_t)(m0 + ty * 4 + i) * Ncols + n0 + tx * 4 + j], acc[i][j]);
}

__global__ void k_fc3(const float* __restrict__ w, const float* __restrict__ b,
                      float* __restrict__ out) {
    int idx = blockIdx.x * 256 + threadIdx.x;
    if (idx >= NGRF * NC) return;
    int g = idx / NC, j = idx % NC;
    float s = b[j];
    #pragma unroll 8
    for (int k = 0; k < 128; k++) s += g_f2[g * 128 + k] * w[k * NC + j];
    out[idx] = s;
}

// ---------------- launch ----------------
extern "C" void kernel_launch(void* const* d_in, const int* in_sizes, int n_in,
                              void* d_out, int out_size) {
    const float* x    = (const float*)d_in[0];
    const int*   ei   = (const int*)  d_in[1];
    const float* ew   = (const float*)d_in[2];
    const float* W10  = (const float*)d_in[3];
    const float* W11  = (const float*)d_in[4];
    const float* b1   = (const float*)d_in[5];
    const float* W20  = (const float*)d_in[6];
    const float* W21  = (const float*)d_in[7];
    const float* b2   = (const float*)d_in[8];
    const float* W30  = (const float*)d_in[9];
    const float* W31  = (const float*)d_in[10];
    const float* b3   = (const float*)d_in[11];
    const float* fc1w = (const float*)d_in[12];
    const float* fc1b = (const float*)d_in[13];
    const float* fc2w = (const float*)d_in[14];
    const float* fc2b = (const float*)d_in[15];
    const float* fc3w = (const float*)d_in[16];
    const float* fc3b = (const float*)d_in[17];
    float* out = (float*)d_out;

    // graph prep + CSR build
    k_init<<<NN / 256, 256>>>();
    k_deg_hist<<<EE / 256, 256>>>(ei, ew);
    k_scan1<<<100, 256>>>();                 // also computes dinv
    k_scan23<<<NN / 256, 256>>>();
    k_scatter<<<EE / 256, 256>>>(ei, ew);

    // layer 1: x[N,64] -> y0:A, y1h ; pull -> C
    k_conv_gemm<64, 32, false, -1, 0><<<NN / 64, 64>>>(x, W10, W11, b1);
    k_pull<32, 0, 2><<<NN / 64, 256>>>();

    // layer 2: relu(C) -> y0:A, y1h ; pull -> C
    k_conv_gemm<32, 32, true, 2, 0><<<NN / 128, 128>>>(nullptr, W20, W21, b2);
    k_pull<32, 0, 2><<<NN / 64, 256>>>();

    // layer 3: relu(C) -> y0:D(16), y1h(16) ; pull -> A-alias(16)
    k_conv_gemm<32, 16, true, 2, 3><<<NN / 128, 64>>>(nullptr, W30, W31, b3);
    k_pull<16, 3, 6><<<NN / 128, 256>>>();

    // fc1: relu(buf6) as [256,6400] @ [6400,256] + b  (split-K = 8)
    k_fc_init<4><<<(256 * 256) / 256, 256>>>(fc1b, 256, 256);
    {
        dim3 grid(4, 4, 8);
        k_fc_gemm<true, 6, 4><<<grid, 256>>>(nullptr, fc1w, 256, 256, 6400, 800);
    }
    // fc2: [256,256] @ [256,128] + b  (split-K = 4)
    k_fc_init<5><<<(256 * 128) / 256, 256>>>(fc2b, 256, 128);
    {
        dim3 grid(2, 4, 4);
        k_fc_gemm<false, 4, 5><<<grid, 256>>>(nullptr, fc2w, 256, 128, 256, 64);
    }
    // fc3: [256,128] @ [128,9] + b -> out
    k_fc3<<<(NGRF * NC + 255) / 256, 256>>>(fc3w, fc3b, out);
}

// round 5
// speedup vs baseline: 1.3316x; 1.0256x over previous
#include <cuda_runtime.h>
#include <cuda_fp16.h>
#include <cstddef>

// ---------------- problem constants ----------------
constexpr int NN   = 102400;    // nodes
constexpr int EE   = 3276800;   // edges
constexpr int NGRF = 256;       // graphs
constexpr int NC   = 9;         // classes

// ---------------- device scratch (no allocs allowed) ----------------
__device__ float  g_deg[NN];            // degree sum, then dinv in-place
__device__ int    g_cnt[NN];            // in-degree histogram
__device__ int    g_off[NN + 1];        // CSR offsets (by dst)
__device__ int    g_rank[EE];           // edge rank within its dst bucket
__device__ int    g_bsum[128];          // scan block sums
__device__ int4   g_csr_pair[EE / 2];   // {src, ew_bits} pairs, 16B-aligned view
__device__ __half g_y1h[NN * 32];       // fp16 gather operand z = dinv[s]*y1[s]
__device__ float4 g_bufA[NN * 8];       // [N,32]  (also 16-wide alias id 6)
__device__ float4 g_bufC[NN * 8];       // [N,32]
__device__ float4 g_bufD[NN * 4];       // [N,16]
__device__ float  g_f1[256 * 256];
__device__ float  g_f2[256 * 128];

__device__ __forceinline__ float* buf_ptr(int id) {
    switch (id) {
        case 0: return reinterpret_cast<float*>(g_bufA);
        case 2: return reinterpret_cast<float*>(g_bufC);
        case 3: return reinterpret_cast<float*>(g_bufD);
        case 4: return g_f1;
        case 5: return g_f2;
        default: return reinterpret_cast<float*>(g_bufA);  // 6: 16-wide alias of A
    }
}

// ---------------- graph prep ----------------
__global__ void k_init() {
    int i = blockIdx.x * 256 + threadIdx.x;
    if (i < NN) { g_deg[i] = 0.f; g_cnt[i] = 0; }
}

// degree by src (weighted) + in-degree histogram by dst, recording each
// edge's rank within its dst bucket (the atomic's return value is free).
__global__ void k_deg_hist(const int* __restrict__ ei, const float* __restrict__ ew) {
    int e = blockIdx.x * 256 + threadIdx.x;
    if (e < EE) {
        atomicAdd(&g_deg[ei[e]], ew[e]);
        g_rank[e] = atomicAdd(&g_cnt[ei[EE + e]], 1);
    }
}

// ---- scan of g_cnt[NN] into g_off (+ fused dinv) ----
__global__ void k_scan1() {
    __shared__ int wsum[8];
    int base = blockIdx.x * 1024 + threadIdx.x * 4;
    {   // fused: deg -> dinv over the same range
        float4 d = *reinterpret_cast<const float4*>(&g_deg[base]);
        d.x = (d.x > 0.f) ? rsqrtf(d.x) : 0.f;
        d.y = (d.y > 0.f) ? rsqrtf(d.y) : 0.f;
        d.z = (d.z > 0.f) ? rsqrtf(d.z) : 0.f;
        d.w = (d.w > 0.f) ? rsqrtf(d.w) : 0.f;
        *reinterpret_cast<float4*>(&g_deg[base]) = d;
    }
    int4 v = *reinterpret_cast<const int4*>(&g_cnt[base]);
    int s1 = v.x, s2 = s1 + v.y, s3 = s2 + v.z, tsum = s3 + v.w;
    int lane = threadIdx.x & 31, wid = threadIdx.x >> 5;
    int inc = tsum;
    #pragma unroll
    for (int o = 1; o < 32; o <<= 1) {
        int n = __shfl_up_sync(0xFFFFFFFFu, inc, o);
        if (lane >= o) inc += n;
    }
    if (lane == 31) wsum[wid] = inc;
    __syncthreads();
    int wpre = 0;
    #pragma unroll
    for (int i = 0; i < 8; i++) if (i < wid) wpre += wsum[i];
    int excl = wpre + inc - tsum;
    g_off[base + 0] = excl;
    g_off[base + 1] = excl + s1;
    g_off[base + 2] = excl + s2;
    g_off[base + 3] = excl + s3;
    if (threadIdx.x == 255) g_bsum[blockIdx.x] = wpre + inc;
}

// level 2+3 fused: each block adds the prefix of g_bsum for its scan1-region
__global__ void k_scan23() {
    const int i = blockIdx.x * 256 + threadIdx.x;
    const int blk = blockIdx.x >> 2;   // scan1 block index (1024 nodes each)
    const int lane = threadIdx.x & 31;
    int partial = 0;
    for (int t = lane; t < blk; t += 32) partial += g_bsum[t];
    #pragma unroll
    for (int o = 16; o; o >>= 1) partial += __shfl_xor_sync(0xFFFFFFFFu, partial, o);
    g_off[i] += partial;
    if (i == 0) g_off[NN] = EE;
}

// atomic-free scatter: pos = off[dst] + rank[e]; stores RAW edge weight
// (dinv factors are folded into z on the src side and the pull epilogue on dst)
__global__ void k_scatter(const int* __restrict__ ei, const float* __restrict__ ew) {
    int e = blockIdx.x * 256 + threadIdx.x;
    if (e >= EE) return;
    int s = ei[e];
    int d = ei[EE + e];
    reinterpret_cast<int2*>(g_csr_pair)[g_off[d] + g_rank[e]] =
        make_int2(s, __float_as_int(ew[e]));
}

// ---------------- conv projection GEMM ----------------
// y0 = relu?(h) @ W0 + b  (fp32) ;  z = dinv * (relu?(h) @ W1)  (fp16 -> g_y1h)
template<int IN, int OUT, bool RELU, int HSRC, int Y0DST>
__global__ void k_conv_gemm(const float* __restrict__ hx,
                            const float* __restrict__ W0g,
                            const float* __restrict__ W1g,
                            const float* __restrict__ bg)
{
    constexpr int NT  = (IN == 64) ? 64 : 128;
    constexpr int NGr = NT / 4;
    constexpr int JG  = OUT / 8;
    constexpr int TPB = NGr * JG;

    __shared__ float sh[NT][IN + 1];
    __shared__ float sW0[IN * OUT];
    __shared__ float sW1[IN * OUT];
    __shared__ float sb[OUT];

    const float* hin = (HSRC < 0) ? hx : buf_ptr(HSRC);
    float* y0 = buf_ptr(Y0DST);
    const int node0 = blockIdx.x * NT;

    for (int i = threadIdx.x; i < IN * OUT; i += TPB) {
        sW0[i] = W0g[i];
        sW1[i] = W1g[i];
    }
    if (threadIdx.x < OUT) sb[threadIdx.x] = bg[threadIdx.x];

    for (int i = threadIdx.x; i < NT * (IN / 4); i += TPB) {
        int n  = i / (IN / 4);
        int k4 = (i % (IN / 4)) * 4;
        float4 v = *reinterpret_cast<const float4*>(&hin[(size_t)(node0 + n) * IN + k4]);
        if (RELU) {
            v.x = fmaxf(v.x, 0.f); v.y = fmaxf(v.y, 0.f);
            v.z = fmaxf(v.z, 0.f); v.w = fmaxf(v.w, 0.f);
        }
        sh[n][k4 + 0] = v.x; sh[n][k4 + 1] = v.y;
        sh[n][k4 + 2] = v.z; sh[n][k4 + 3] = v.w;
    }
    __syncthreads();

    const int g  = threadIdx.x % NGr;
    const int j0 = (threadIdx.x / NGr) * 8;

    float a0[4][8], a1[4][8];
    #pragma unroll
    for (int n = 0; n < 4; n++)
        #pragma unroll
        for (int j = 0; j < 8; j++) { a0[n][j] = 0.f; a1[n][j] = 0.f; }

    #pragma unroll 4
    for (int k = 0; k < IN; k++) {
        float hh[4];
        #pragma unroll
        for (int n = 0; n < 4; n++) hh[n] = sh[g * 4 + n][k];
        float w0[8], w1[8];
        reinterpret_cast<float4*>(w0)[0] = reinterpret_cast<const float4*>(&sW0[k * OUT + j0])[0];
        reinterpret_cast<float4*>(w0)[1] = reinterpret_cast<const float4*>(&sW0[k * OUT + j0])[1];
        reinterpret_cast<float4*>(w1)[0] = reinterpret_cast<const float4*>(&sW1[k * OUT + j0])[0];
        reinterpret_cast<float4*>(w1)[1] = reinterpret_cast<const float4*>(&sW1[k * OUT + j0])[1];
        #pragma unroll
        for (int n = 0; n < 4; n++)
            #pragma unroll
            for (int j = 0; j < 8; j++) {
                a0[n][j] += hh[n] * w0[j];
                a1[n][j] += hh[n] * w1[j];
            }
    }

    #pragma unroll
    for (int n = 0; n < 4; n++) {
        int node = node0 + g * 4 + n;
        const float dn = g_deg[node];          // dinv[node]
        float4 o0a, o0b;
        o0a.x = a0[n][0] + sb[j0 + 0]; o0a.y = a0[n][1] + sb[j0 + 1];
        o0a.z = a0[n][2] + sb[j0 + 2]; o0a.w = a0[n][3] + sb[j0 + 3];
        o0b.x = a0[n][4] + sb[j0 + 4]; o0b.y = a0[n][5] + sb[j0 + 5];
        o0b.z = a0[n][6] + sb[j0 + 6]; o0b.w = a0[n][7] + sb[j0 + 7];
        *reinterpret_cast<float4*>(&y0[(size_t)node * OUT + j0])     = o0a;
        *reinterpret_cast<float4*>(&y0[(size_t)node * OUT + j0 + 4]) = o0b;
        // z = dinv * y1 -> fp16, 8 values = one 16B store
        __half2 h01 = __float22half2_rn(make_float2(dn * a1[n][0], dn * a1[n][1]));
        __half2 h23 = __float22half2_rn(make_float2(dn * a1[n][2], dn * a1[n][3]));
        __half2 h45 = __float22half2_rn(make_float2(dn * a1[n][4], dn * a1[n][5]));
        __half2 h67 = __float22half2_rn(make_float2(dn * a1[n][6], dn * a1[n][7]));
        uint4 pk;
        pk.x = *reinterpret_cast<unsigned*>(&h01);
        pk.y = *reinterpret_cast<unsigned*>(&h23);
        pk.z = *reinterpret_cast<unsigned*>(&h45);
        pk.w = *reinterpret_cast<unsigned*>(&h67);
        *reinterpret_cast<uint4*>(&g_y1h[(size_t)node * OUT + j0]) = pk;
    }
}

// ---------------- pull aggregation ----------------
// out[n] = y0[n] - dinv[n] * sum_e w_e * z[src_e]
// W/8 threads per node; 8 edges per round (4x int4 CSR loads + 8 gathers, MLP~12).
__device__ __forceinline__ void acc8(float* a, uint4 r, float w) {
    float2 f0 = __half22float2(*reinterpret_cast<__half2*>(&r.x));
    float2 f1 = __half22float2(*reinterpret_cast<__half2*>(&r.y));
    float2 f2 = __half22float2(*reinterpret_cast<__half2*>(&r.z));
    float2 f3 = __half22float2(*reinterpret_cast<__half2*>(&r.w));
    a[0] = fmaf(w, f0.x, a[0]); a[1] = fmaf(w, f0.y, a[1]);
    a[2] = fmaf(w, f1.x, a[2]); a[3] = fmaf(w, f1.y, a[3]);
    a[4] = fmaf(w, f2.x, a[4]); a[5] = fmaf(w, f2.y, a[5]);
    a[6] = fmaf(w, f3.x, a[6]); a[7] = fmaf(w, f3.y, a[7]);
}

template<int W, int Y0SRC, int DST>
__global__ void k_pull() {
    constexpr int TPN = W / 8;                 // threads per node
    constexpr int NPB = 256 / TPN;             // nodes per block
    const int n = blockIdx.x * NPB + threadIdx.x / TPN;
    const int c = threadIdx.x % TPN;           // 8-feature chunk
    const float* __restrict__ y0 = buf_ptr(Y0SRC);
    float* __restrict__ out = buf_ptr(DST);
    const int2* __restrict__ csr = reinterpret_cast<const int2*>(g_csr_pair);

    const int jb = g_off[n];
    const int je = g_off[n + 1];

    float acc[8];
    #pragma unroll
    for (int i = 0; i < 8; i++) acc[i] = 0.f;

    int j = jb;
    if ((j & 1) && j < je) {                   // align to even for int4 loads
        int2 sw = csr[j];
        uint4 r = *reinterpret_cast<const uint4*>(&g_y1h[(size_t)sw.x * W + c * 8]);
        acc8(acc, r, __int_as_float(sw.y));
        j++;
    }
    for (; j + 8 <= je; j += 8) {
        int4 p0 = g_csr_pair[(j >> 1) + 0];
        int4 p1 = g_csr_pair[(j >> 1) + 1];
        int4 p2 = g_csr_pair[(j >> 1) + 2];
        int4 p3 = g_csr_pair[(j >> 1) + 3];
        uint4 r0 = *reinterpret_cast<const uint4*>(&g_y1h[(size_t)p0.x * W + c * 8]);
        uint4 r1 = *reinterpret_cast<const uint4*>(&g_y1h[(size_t)p0.z * W + c * 8]);
        uint4 r2 = *reinterpret_cast<const uint4*>(&g_y1h[(size_t)p1.x * W + c * 8]);
        uint4 r3 = *reinterpret_cast<const uint4*>(&g_y1h[(size_t)p1.z * W + c * 8]);
        uint4 r4 = *reinterpret_cast<const uint4*>(&g_y1h[(size_t)p2.x * W + c * 8]);
        uint4 r5 = *reinterpret_cast<const uint4*>(&g_y1h[(size_t)p2.z * W + c * 8]);
        uint4 r6 = *reinterpret_cast<const uint4*>(&g_y1h[(size_t)p3.x * W + c * 8]);
        uint4 r7 = *reinterpret_cast<const uint4*>(&g_y1h[(size_t)p3.z * W + c * 8]);
        acc8(acc, r0, __int_as_float(p0.y));
        acc8(acc, r1, __int_as_float(p0.w));
        acc8(acc, r2, __int_as_float(p1.y));
        acc8(acc, r3, __int_as_float(p1.w));
        acc8(acc, r4, __int_as_float(p2.y));
        acc8(acc, r5, __int_as_float(p2.w));
        acc8(acc, r6, __int_as_float(p3.y));
        acc8(acc, r7, __int_as_float(p3.w));
    }
    for (; j + 2 <= je; j += 2) {
        int4 p0 = g_csr_pair[j >> 1];
        uint4 r0 = *reinterpret_cast<const uint4*>(&g_y1h[(size_t)p0.x * W + c * 8]);
        uint4 r1 = *reinterpret_cast<const uint4*>(&g_y1h[(size_t)p0.z * W + c * 8]);
        acc8(acc, r0, __int_as_float(p0.y));
        acc8(acc, r1, __int_as_float(p0.w));
    }
    if (j < je) {
        int2 sw = csr[j];
        uint4 r = *reinterpret_cast<const uint4*>(&g_y1h[(size_t)sw.x * W + c * 8]);
        acc8(acc, r, __int_as_float(sw.y));
    }

    const float mnd = -g_deg[n];               // -dinv[n]
    float4 b0 = *reinterpret_cast<const float4*>(&y0[(size_t)n * W + c * 8]);
    float4 b1 = *reinterpret_cast<const float4*>(&y0[(size_t)n * W + c * 8 + 4]);
    float4 o0 = make_float4(fmaf(mnd, acc[0], b0.x), fmaf(mnd, acc[1], b0.y),
                            fmaf(mnd, acc[2], b0.z), fmaf(mnd, acc[3], b0.w));
    float4 o1 = make_float4(fmaf(mnd, acc[4], b1.x), fmaf(mnd, acc[5], b1.y),
                            fmaf(mnd, acc[6], b1.z), fmaf(mnd, acc[7], b1.w));
    *reinterpret_cast<float4*>(&out[(size_t)n * W + c * 8])     = o0;
    *reinterpret_cast<float4*>(&out[(size_t)n * W + c * 8 + 4]) = o1;
}

// ---------------- FC layers ----------------
template<int CDST>
__global__ void k_fc_init(const float* __restrict__ bias, int M, int Ncols) {
    int i = blockIdx.x * 256 + threadIdx.x;
    if (i < M * Ncols) buf_ptr(CDST)[i] = bias[i % Ncols];
}

template<bool ARELU, int ASRC, int CDST>
__global__ void k_fc_gemm(const float* __restrict__ Aarg,
                          const float* __restrict__ B,
                          int M, int Ncols, int K, int Kper)
{
    const float* A = (ASRC < 0) ? Aarg : buf_ptr(ASRC);
    float* C = buf_ptr(CDST);
    __shared__ float As[8][68];
    __shared__ float Bs[8][64];
    const int n0 = blockIdx.x * 64;
    const int m0 = blockIdx.y * 64;
    const int kbase = blockIdx.z * Kper;
    const int tid = threadIdx.x;
    const int tx = tid % 16, ty = tid / 16;

    float acc[4][4];
    #pragma unroll
    for (int i = 0; i < 4; i++)
        #pragma unroll
        for (int j = 0; j < 4; j++) acc[i][j] = 0.f;

    for (int k0 = kbase; k0 < kbase + Kper; k0 += 8) {
        #pragma unroll
        for (int r = 0; r < 2; r++) {
            int idx = tid + r * 256;
            int mm = idx >> 3, kk = idx & 7;
            float v = A[(size_t)(m0 + mm) * K + k0 + kk];
            if (ARELU) v = fmaxf(v, 0.f);
            As[kk][mm] = v;
        }
        #pragma unroll
        for (int r = 0; r < 2; r++) {
            int idx = tid + r * 256;
            int kk = idx >> 6, nn = idx & 63;
            Bs[kk][nn] = B[(size_t)(k0 + kk) * Ncols + n0 + nn];
        }
        __syncthreads();
        #pragma unroll
        for (int kk = 0; kk < 8; kk++) {
            float4 a4 = *reinterpret_cast<const float4*>(&As[kk][ty * 4]);
            float4 b4 = *reinterpret_cast<const float4*>(&Bs[kk][tx * 4]);
            float a[4] = {a4.x, a4.y, a4.z, a4.w};
            float b[4] = {b4.x, b4.y, b4.z, b4.w};
            #pragma unroll
            for (int i = 0; i < 4; i++)
                #pragma unroll
                for (int j = 0; j < 4; j++) acc[i][j] += a[i] * b[j];
        }
        __syncthreads();
    }
    #pragma unroll
    for (int i = 0; i < 4; i++)
        #pragma unroll
        for (int j = 0; j < 4; j++)
            atomicAdd(&C[(size_t)(m0 + ty * 4 + i) * Ncols + n0 + tx * 4 + j], acc[i][j]);
}

__global__ void k_fc3(const float* __restrict__ w, const float* __restrict__ b,
                      float* __restrict__ out) {
    int idx = blockIdx.x * 256 + threadIdx.x;
    if (idx >= NGRF * NC) return;
    int g = idx / NC, j = idx % NC;
    float s = b[j];
    #pragma unroll 8
    for (int k = 0; k < 128; k++) s += g_f2[g * 128 + k] * w[k * NC + j];
    out[idx] = s;
}

// ---------------- launch ----------------
extern "C" void kernel_launch(void* const* d_in, const int* in_sizes, int n_in,
                              void* d_out, int out_size) {
    const float* x    = (const float*)d_in[0];
    const int*   ei   = (const int*)  d_in[1];
    const float* ew   = (const float*)d_in[2];
    const float* W10  = (const float*)d_in[3];
    const float* W11  = (const float*)d_in[4];
    const float* b1   = (const float*)d_in[5];
    const float* W20  = (const float*)d_in[6];
    const float* W21  = (const float*)d_in[7];
    const float* b2   = (const float*)d_in[8];
    const float* W30  = (const float*)d_in[9];
    const float* W31  = (const float*)d_in[10];
    const float* b3   = (const float*)d_in[11];
    const float* fc1w = (const float*)d_in[12];
    const float* fc1b = (const float*)d_in[13];
    const float* fc2w = (const float*)d_in[14];
    const float* fc2b = (const float*)d_in[15];
    const float* fc3w = (const float*)d_in[16];
    const float* fc3b = (const float*)d_in[17];
    float* out = (float*)d_out;

    // graph prep + CSR build
    k_init<<<NN / 256, 256>>>();
    k_deg_hist<<<EE / 256, 256>>>(ei, ew);
    k_scan1<<<100, 256>>>();                 // also computes dinv
    k_scan23<<<NN / 256, 256>>>();
    k_scatter<<<EE / 256, 256>>>(ei, ew);

    // layer 1: x[N,64] -> y0:A, z ; pull -> C
    k_conv_gemm<64, 32, false, -1, 0><<<NN / 64, 64>>>(x, W10, W11, b1);
    k_pull<32, 0, 2><<<NN / 64, 256>>>();

    // layer 2: relu(C) -> y0:A, z ; pull -> C
    k_conv_gemm<32, 32, true, 2, 0><<<NN / 128, 128>>>(nullptr, W20, W21, b2);
    k_pull<32, 0, 2><<<NN / 64, 256>>>();

    // layer 3: relu(C) -> y0:D(16), z(16) ; pull -> A-alias(16)
    k_conv_gemm<32, 16, true, 2, 3><<<NN / 128, 64>>>(nullptr, W30, W31, b3);
    k_pull<16, 3, 6><<<NN / 128, 256>>>();

    // fc1: relu(buf6) as [256,6400] @ [6400,256] + b  (split-K = 8)
    k_fc_init<4><<<(256 * 256) / 256, 256>>>(fc1b, 256, 256);
    {
        dim3 grid(4, 4, 8);
        k_fc_gemm<true, 6, 4><<<grid, 256>>>(nullptr, fc1w, 256, 256, 6400, 800);
    }
    // fc2: [256,256] @ [256,128] + b  (split-K = 4)
    k_fc_init<5><<<(256 * 128) / 256, 256>>>(fc2b, 256, 128);
    {
        dim3 grid(2, 4, 4);
        k_fc_gemm<false, 4, 5><<<grid, 256>>>(nullptr, fc2w, 256, 128, 256, 64);
    }
    // fc3: [256,128] @ [128,9] + b -> out
    k_fc3<<<(NGRF * NC + 255) / 256, 256>>>(fc3w, fc3b, out);
}